// round 1
// baseline (speedup 1.0000x reference)
#include <cuda_runtime.h>
#include <math.h>

// Problem constants
#define B_   4
#define LQ_  2048
#define LK_  2048
#define IND  1024
#define NH_  16
#define HD_  64
#define HDA  1024
#define NEGV (-1e9f)

// Scratch (device globals — no allocation allowed)
__device__ float  g_Qh[(size_t)B_ * NH_ * LQ_ * HD_];   // [b,h,q,d], pre-scaled by 1/8
__device__ float  g_Kh[(size_t)B_ * NH_ * LK_ * HD_];   // [b,h,k,d]
__device__ float  g_Vh[(size_t)B_ * NH_ * LK_ * HD_];   // [b,h,k,d]
__device__ float  g_Oh[(size_t)B_ * LQ_ * HDA];         // [b,q,h*d]
__device__ float2 g_stats[(size_t)B_ * NH_ * LQ_];      // {rowmax, 1/rowsum}

// ---------------------------------------------------------------------------
// Projection GEMM: Y = alpha * (X @ W^T + bias), X [M=8192, K=1024],
// W [N=1024, K=1024], output scattered to [b,h,l,d] layout.
// 128x128 tile, BK=8, 256 threads, 8x8 microtile.
// ---------------------------------------------------------------------------
__global__ __launch_bounds__(256) void proj_kernel(
    const float* __restrict__ X, const float* __restrict__ W,
    const float* __restrict__ bias, float* __restrict__ Y, float alpha)
{
    const int bm = blockIdx.y * 128;
    const int bn = blockIdx.x * 128;
    __shared__ float As[8][132];
    __shared__ float Ws[8][132];
    const int t  = threadIdx.x;
    const int tx = t % 16, ty = t / 16;
    const int lk = t % 8,  lm = t / 8;   // loader coords

    float acc[8][8];
    #pragma unroll
    for (int i = 0; i < 8; i++)
        #pragma unroll
        for (int j = 0; j < 8; j++) acc[i][j] = 0.f;

    const float* Xp = X + (size_t)(bm + lm) * IND + lk;
    const float* Wp = W + (size_t)(bn + lm) * IND + lk;

    for (int kt = 0; kt < IND; kt += 8) {
        #pragma unroll
        for (int i = 0; i < 4; i++) {
            As[lk][lm + 32 * i] = Xp[(size_t)(32 * i) * IND + kt];
            Ws[lk][lm + 32 * i] = Wp[(size_t)(32 * i) * IND + kt];
        }
        __syncthreads();
        #pragma unroll
        for (int kk = 0; kk < 8; kk++) {
            float a[8], b[8];
            #pragma unroll
            for (int i = 0; i < 8; i++) a[i] = As[kk][ty * 8 + i];
            #pragma unroll
            for (int j = 0; j < 8; j++) b[j] = Ws[kk][tx + 16 * j];
            #pragma unroll
            for (int i = 0; i < 8; i++)
                #pragma unroll
                for (int j = 0; j < 8; j++) acc[i][j] += a[i] * b[j];
        }
        __syncthreads();
    }

    #pragma unroll
    for (int i = 0; i < 8; i++) {
        const int m  = bm + ty * 8 + i;
        const int bb = m / LQ_, l = m % LQ_;
        #pragma unroll
        for (int j = 0; j < 8; j++) {
            const int n = bn + tx + 16 * j;
            const int h = n / HD_, dd = n % HD_;
            Y[(((size_t)bb * NH_ + h) * LQ_ + l) * HD_ + dd] =
                alpha * (acc[i][j] + bias[n]);
        }
    }
}

// ---------------------------------------------------------------------------
// QK^T batched GEMM: per z=(b,h): S[m,n] = sum_d Q[m,d]*K[n,d] (Q pre-scaled),
// masked to NEGV where mask==0. Writes raw logits to scores region of d_out.
// ---------------------------------------------------------------------------
__global__ __launch_bounds__(256) void qk_kernel(
    const int* __restrict__ mask, float* __restrict__ S)
{
    const int z  = blockIdx.z;
    const int bm = blockIdx.y * 128;
    const int bn = blockIdx.x * 128;
    const float* A  = g_Qh + (size_t)z * LQ_ * HD_;
    const float* Bp = g_Kh + (size_t)z * LK_ * HD_;

    __shared__ float As[8][132];
    __shared__ float Ws[8][132];
    const int t  = threadIdx.x;
    const int tx = t % 16, ty = t / 16;
    const int lk = t % 8,  lm = t / 8;

    float acc[8][8];
    #pragma unroll
    for (int i = 0; i < 8; i++)
        #pragma unroll
        for (int j = 0; j < 8; j++) acc[i][j] = 0.f;

    for (int kt = 0; kt < HD_; kt += 8) {
        #pragma unroll
        for (int i = 0; i < 4; i++) {
            As[lk][lm + 32 * i] = A [(size_t)(bm + lm + 32 * i) * HD_ + kt + lk];
            Ws[lk][lm + 32 * i] = Bp[(size_t)(bn + lm + 32 * i) * HD_ + kt + lk];
        }
        __syncthreads();
        #pragma unroll
        for (int kk = 0; kk < 8; kk++) {
            float a[8], b[8];
            #pragma unroll
            for (int i = 0; i < 8; i++) a[i] = As[kk][ty * 8 + i];
            #pragma unroll
            for (int j = 0; j < 8; j++) b[j] = Ws[kk][tx + 16 * j];
            #pragma unroll
            for (int i = 0; i < 8; i++)
                #pragma unroll
                for (int j = 0; j < 8; j++) acc[i][j] += a[i] * b[j];
        }
        __syncthreads();
    }

    float* Sz = S + (size_t)z * LQ_ * LK_;
    #pragma unroll
    for (int i = 0; i < 8; i++) {
        const int m = bm + ty * 8 + i;
        #pragma unroll
        for (int j = 0; j < 8; j++) {
            const int n = bn + tx + 16 * j;
            const float v = acc[i][j];
            Sz[(size_t)m * LK_ + n] = mask[(size_t)m * LK_ + n] ? v : NEGV;
        }
    }
}

// ---------------------------------------------------------------------------
// Row softmax stats: one block per (z, q) row. Stores {max, 1/sum(exp)}.
// ---------------------------------------------------------------------------
__global__ __launch_bounds__(256) void stats_kernel(const float* __restrict__ S)
{
    const size_t r = blockIdx.x;
    const float* row = S + r * LK_;
    const int t = threadIdx.x;
    __shared__ float red[256];

    float mx = -3.4e38f;
    for (int i = t; i < LK_; i += 256) mx = fmaxf(mx, row[i]);
    red[t] = mx; __syncthreads();
    for (int s = 128; s > 0; s >>= 1) {
        if (t < s) red[t] = fmaxf(red[t], red[t + s]);
        __syncthreads();
    }
    mx = red[0]; __syncthreads();

    float sm = 0.f;
    for (int i = t; i < LK_; i += 256) sm += __expf(row[i] - mx);
    red[t] = sm; __syncthreads();
    for (int s = 128; s > 0; s >>= 1) {
        if (t < s) red[t] += red[t + s];
        __syncthreads();
    }
    if (t == 0) g_stats[r] = make_float2(mx, 1.0f / red[0]);
}

// ---------------------------------------------------------------------------
// PV GEMM fused with softmax normalization: reads raw logits, computes
// p = exp(s-max)/sum, writes p back to d_out scores (final output), and
// accumulates Oh = P @ V into [b,q,h*d] layout.
// Tile: 128(M) x 64(N=full head dim) x 16(K), 256 threads, 8x4 microtile.
// ---------------------------------------------------------------------------
__global__ __launch_bounds__(256) void pv_kernel(float* __restrict__ S)
{
    const int z  = blockIdx.z;
    const int bm = blockIdx.x * 128;
    const float* V = g_Vh + (size_t)z * LK_ * HD_;
    float* Sz = S + (size_t)z * LQ_ * LK_;

    __shared__ float Ps[16][132];
    __shared__ float Vs[16][68];
    const int t  = threadIdx.x;
    const int tx = t % 16, ty = t / 16;
    const int lk = t % 16, lr = t / 16;

    float acc[8][4];
    #pragma unroll
    for (int i = 0; i < 8; i++)
        #pragma unroll
        for (int j = 0; j < 4; j++) acc[i][j] = 0.f;

    for (int kt = 0; kt < LK_; kt += 16) {
        #pragma unroll
        for (int i = 0; i < 8; i++) {
            const int m = i * 16 + lr;
            const float2 st = g_stats[(size_t)z * LQ_ + bm + m];
            const size_t off = (size_t)(bm + m) * LK_ + kt + lk;
            const float p = __expf(Sz[off] - st.x) * st.y;
            Sz[off] = p;                 // final normalized scores output
            Ps[lk][m] = p;
        }
        #pragma unroll
        for (int i = 0; i < 4; i++) {
            const int kk = i * 4 + t / 64;
            const int n  = t % 64;
            Vs[kk][n] = V[(size_t)(kt + kk) * HD_ + n];
        }
        __syncthreads();
        #pragma unroll
        for (int kk = 0; kk < 16; kk++) {
            float a[8], b[4];
            #pragma unroll
            for (int i = 0; i < 8; i++) a[i] = Ps[kk][ty * 8 + i];
            #pragma unroll
            for (int j = 0; j < 4; j++) b[j] = Vs[kk][tx + 16 * j];
            #pragma unroll
            for (int i = 0; i < 8; i++)
                #pragma unroll
                for (int j = 0; j < 4; j++) acc[i][j] += a[i] * b[j];
        }
        __syncthreads();
    }

    const int bb = z / NH_, h = z % NH_;
    #pragma unroll
    for (int i = 0; i < 8; i++) {
        const int qrow = bm + ty * 8 + i;
        float* orow = g_Oh + ((size_t)bb * LQ_ + qrow) * HDA + h * HD_;
        #pragma unroll
        for (int j = 0; j < 4; j++) orow[tx + 16 * j] = acc[i][j];
    }
}

// ---------------------------------------------------------------------------
// Output GEMM: out = Oh @ wo^T + bo, M=8192, N=64, K=1024.
// Tile 64x64x16, 256 threads, 4x4 microtile.
// ---------------------------------------------------------------------------
__global__ __launch_bounds__(256) void o_kernel(
    const float* __restrict__ wo, const float* __restrict__ bo,
    float* __restrict__ out)
{
    const int bm = blockIdx.x * 64;
    __shared__ float As[16][68];
    __shared__ float Ws[16][68];
    const int t  = threadIdx.x;
    const int tx = t % 16, ty = t / 16;
    const int lk = t % 16, lr = t / 16;

    float acc[4][4];
    #pragma unroll
    for (int i = 0; i < 4; i++)
        #pragma unroll
        for (int j = 0; j < 4; j++) acc[i][j] = 0.f;

    for (int kt = 0; kt < HDA; kt += 16) {
        #pragma unroll
        for (int i = 0; i < 4; i++) {
            const int m = i * 16 + lr;
            As[lk][m] = g_Oh[(size_t)(bm + m) * HDA + kt + lk];
            Ws[lk][m] = wo  [(size_t)m        * HDA + kt + lk];
        }
        __syncthreads();
        #pragma unroll
        for (int kk = 0; kk < 16; kk++) {
            float a[4], b[4];
            #pragma unroll
            for (int i = 0; i < 4; i++) a[i] = As[kk][ty * 4 + i];
            #pragma unroll
            for (int j = 0; j < 4; j++) b[j] = Ws[kk][tx + 16 * j];
            #pragma unroll
            for (int i = 0; i < 4; i++)
                #pragma unroll
                for (int j = 0; j < 4; j++) acc[i][j] += a[i] * b[j];
        }
        __syncthreads();
    }

    #pragma unroll
    for (int i = 0; i < 4; i++) {
        const int m = bm + ty * 4 + i;
        #pragma unroll
        for (int j = 0; j < 4; j++) {
            const int n = tx + 16 * j;
            out[(size_t)m * HD_ + n] = acc[i][j] + bo[n];
        }
    }
}

// ---------------------------------------------------------------------------
extern "C" void kernel_launch(void* const* d_in, const int* in_sizes, int n_in,
                              void* d_out, int out_size)
{
    (void)in_sizes; (void)n_in; (void)out_size;
    const float* q    = (const float*)d_in[0];
    const float* k    = (const float*)d_in[1];
    const float* v    = (const float*)d_in[2];
    const int*   mask = (const int*)  d_in[3];
    const float* wq   = (const float*)d_in[4];
    const float* bq   = (const float*)d_in[5];
    const float* wk   = (const float*)d_in[6];
    const float* bk   = (const float*)d_in[7];
    const float* wv   = (const float*)d_in[8];
    const float* bv   = (const float*)d_in[9];
    const float* wo   = (const float*)d_in[10];
    const float* bo   = (const float*)d_in[11];

    float* out    = (float*)d_out;                       // [B, LQ, 64]
    float* scores = out + (size_t)B_ * LQ_ * HD_;        // [B, H, LQ, LK]

    float *Qh, *Kh, *Vh;
    cudaGetSymbolAddress((void**)&Qh, g_Qh);
    cudaGetSymbolAddress((void**)&Kh, g_Kh);
    cudaGetSymbolAddress((void**)&Vh, g_Vh);

    const dim3 blk(256);
    const dim3 gproj(IND / 128, (B_ * LQ_) / 128);       // (8, 64)
    proj_kernel<<<gproj, blk>>>(q, wq, bq, Qh, 0.125f);  // 1/sqrt(64)
    proj_kernel<<<gproj, blk>>>(k, wk, bk, Kh, 1.0f);
    proj_kernel<<<gproj, blk>>>(v, wv, bv, Vh, 1.0f);

    const dim3 gqk(LK_ / 128, LQ_ / 128, B_ * NH_);      // (16,16,64)
    qk_kernel<<<gqk, blk>>>(mask, scores);

    stats_kernel<<<B_ * NH_ * LQ_, 256>>>(scores);       // 131072 blocks

    const dim3 gpv(LQ_ / 128, 1, B_ * NH_);              // (16,1,64)
    pv_kernel<<<gpv, blk>>>(scores);

    o_kernel<<<(B_ * LQ_) / 64, blk>>>(wo, bo, out);     // 128 blocks
}

// round 2
// speedup vs baseline: 1.5405x; 1.5405x over previous
#include <cuda_runtime.h>
#include <math.h>

#define B_   4
#define LQ_  2048
#define LK_  2048
#define IND  1024
#define NH_  16
#define HD_  64
#define HDA  1024
#define NZ   (B_*NH_)
#define NEGV (-1e9f)

// Scratch (device globals — no allocation allowed)
__device__ float  g_Qh[(size_t)NZ * HD_ * LQ_];   // [z][d][q]  (transposed, pre-scaled)
__device__ float  g_Kh[(size_t)NZ * HD_ * LK_];   // [z][d][k]  (transposed)
__device__ float  g_Vh[(size_t)NZ * LK_ * HD_];   // [z][k][d]
__device__ float  g_Oh[(size_t)B_ * LQ_ * HDA];   // [b][q][h*d]
__device__ float2 g_part[(size_t)NZ * 16 * LQ_];  // per-(z, n-tile, row) {max, expsum}
__device__ float2 g_stats[(size_t)NZ * LQ_];      // {rowmax, 1/rowsum}

// ---------------------------------------------------------------------------
// Projection GEMM: Y = alpha*(X @ W^T + bias). X [8192,1024], W [1024,1024].
// 128x128x16 tile, 256 threads, 8x8 microtile, float4 everywhere,
// register-staged global prefetch. transposed=1 -> Y[z][d][l], else Y[z][l][d].
// ---------------------------------------------------------------------------
__global__ __launch_bounds__(256) void proj_kernel(
    const float* __restrict__ X, const float* __restrict__ W,
    const float* __restrict__ bias, float* __restrict__ Y,
    float alpha, int transposed)
{
    const int bm = blockIdx.y * 128;
    const int bn = blockIdx.x * 128;
    __shared__ float As[16][132];
    __shared__ float Bs[16][132];
    const int t  = threadIdx.x;
    const int tx = t & 15, ty = t >> 4;
    const int r  = t >> 1, half = t & 1;   // loader: row r, col-octet half

    const float* Ap = X + (size_t)(bm + r) * IND + half * 8;
    const float* Bp = W + (size_t)(bn + r) * IND + half * 8;

    float4 a0 = *(const float4*)(Ap);
    float4 a1 = *(const float4*)(Ap + 4);
    float4 b0 = *(const float4*)(Bp);
    float4 b1 = *(const float4*)(Bp + 4);

    float acc[8][8];
    #pragma unroll
    for (int i = 0; i < 8; i++)
        #pragma unroll
        for (int j = 0; j < 8; j++) acc[i][j] = 0.f;

    for (int kt = 0; kt < IND; kt += 16) {
        const int c = half * 8;
        As[c+0][r]=a0.x; As[c+1][r]=a0.y; As[c+2][r]=a0.z; As[c+3][r]=a0.w;
        As[c+4][r]=a1.x; As[c+5][r]=a1.y; As[c+6][r]=a1.z; As[c+7][r]=a1.w;
        Bs[c+0][r]=b0.x; Bs[c+1][r]=b0.y; Bs[c+2][r]=b0.z; Bs[c+3][r]=b0.w;
        Bs[c+4][r]=b1.x; Bs[c+5][r]=b1.y; Bs[c+6][r]=b1.z; Bs[c+7][r]=b1.w;
        __syncthreads();
        if (kt + 16 < IND) {
            a0 = *(const float4*)(Ap + kt + 16);
            a1 = *(const float4*)(Ap + kt + 20);
            b0 = *(const float4*)(Bp + kt + 16);
            b1 = *(const float4*)(Bp + kt + 20);
        }
        #pragma unroll
        for (int kk = 0; kk < 16; kk++) {
            float4 x0 = *(const float4*)&As[kk][ty * 8];
            float4 x1 = *(const float4*)&As[kk][ty * 8 + 4];
            float4 y0 = *(const float4*)&Bs[kk][tx * 8];
            float4 y1 = *(const float4*)&Bs[kk][tx * 8 + 4];
            float a[8] = {x0.x,x0.y,x0.z,x0.w,x1.x,x1.y,x1.z,x1.w};
            float b[8] = {y0.x,y0.y,y0.z,y0.w,y1.x,y1.y,y1.z,y1.w};
            #pragma unroll
            for (int i = 0; i < 8; i++)
                #pragma unroll
                for (int j = 0; j < 8; j++) acc[i][j] += a[i] * b[j];
        }
        __syncthreads();
    }

    if (!transposed) {
        // Y[z][l][d] (for V): thread cols are 8 contiguous channels in one head
        #pragma unroll
        for (int i = 0; i < 8; i++) {
            const int m  = bm + ty * 8 + i;
            const int bb = m >> 11, l = m & 2047;
            const int n0 = bn + tx * 8;
            const int h  = n0 >> 6, dd = n0 & 63;
            float* dst = Y + (((size_t)(bb * NH_ + h) * LK_) + l) * HD_ + dd;
            float4 o0, o1;
            o0.x = alpha * (acc[i][0] + bias[n0+0]);
            o0.y = alpha * (acc[i][1] + bias[n0+1]);
            o0.z = alpha * (acc[i][2] + bias[n0+2]);
            o0.w = alpha * (acc[i][3] + bias[n0+3]);
            o1.x = alpha * (acc[i][4] + bias[n0+4]);
            o1.y = alpha * (acc[i][5] + bias[n0+5]);
            o1.z = alpha * (acc[i][6] + bias[n0+6]);
            o1.w = alpha * (acc[i][7] + bias[n0+7]);
            *(float4*)(dst)     = o0;
            *(float4*)(dst + 4) = o1;
        }
    } else {
        // Y[z][d][l] (for Q/K): per channel j, 8 contiguous tokens -> 2x float4
        const int m0 = bm + ty * 8;
        const int bb = m0 >> 11, l0 = m0 & 2047;
        #pragma unroll
        for (int j = 0; j < 8; j++) {
            const int n  = bn + tx * 8 + j;
            const int h  = n >> 6, dd = n & 63;
            float* dst = Y + (((size_t)(bb * NH_ + h) * HD_) + dd) * LQ_ + l0;
            float4 o0, o1;
            o0.x = alpha * (acc[0][j] + bias[n]);
            o0.y = alpha * (acc[1][j] + bias[n]);
            o0.z = alpha * (acc[2][j] + bias[n]);
            o0.w = alpha * (acc[3][j] + bias[n]);
            o1.x = alpha * (acc[4][j] + bias[n]);
            o1.y = alpha * (acc[5][j] + bias[n]);
            o1.z = alpha * (acc[6][j] + bias[n]);
            o1.w = alpha * (acc[7][j] + bias[n]);
            *(float4*)(dst)     = o0;
            *(float4*)(dst + 4) = o1;
        }
    }
}

// ---------------------------------------------------------------------------
// QK^T: S[m,n] = sum_d Qh[z][d][m] * Kh[z][d][n], masked. Writes raw logits
// and per-(block-col-tile, row) partial softmax stats.
// 128x128x16 tile, no transpose needed (operands already d-major).
// ---------------------------------------------------------------------------
__global__ __launch_bounds__(256) void qk_kernel(
    const int* __restrict__ mask, float* __restrict__ S)
{
    const int z  = blockIdx.z;
    const int bm = blockIdx.y * 128;
    const int bn = blockIdx.x * 128;
    const float* Q = g_Qh + (size_t)z * HD_ * LQ_;
    const float* K = g_Kh + (size_t)z * HD_ * LK_;

    __shared__ float As[16][132];
    __shared__ float Bs[16][132];
    const int t  = threadIdx.x;
    const int tx = t & 15, ty = t >> 4;
    const int dr = t >> 4, g = t & 15;   // loader: d-row, col-octet

    float acc[8][8];
    #pragma unroll
    for (int i = 0; i < 8; i++)
        #pragma unroll
        for (int j = 0; j < 8; j++) acc[i][j] = 0.f;

    for (int kt = 0; kt < HD_; kt += 16) {
        const float* qp = Q + (size_t)(kt + dr) * LQ_ + bm + g * 8;
        const float* kp = K + (size_t)(kt + dr) * LK_ + bn + g * 8;
        float4 qa = *(const float4*)(qp);
        float4 qb = *(const float4*)(qp + 4);
        float4 ka = *(const float4*)(kp);
        float4 kb = *(const float4*)(kp + 4);
        *(float4*)&As[dr][g * 8]     = qa;
        *(float4*)&As[dr][g * 8 + 4] = qb;
        *(float4*)&Bs[dr][g * 8]     = ka;
        *(float4*)&Bs[dr][g * 8 + 4] = kb;
        __syncthreads();
        #pragma unroll
        for (int kk = 0; kk < 16; kk++) {
            float4 x0 = *(const float4*)&As[kk][ty * 8];
            float4 x1 = *(const float4*)&As[kk][ty * 8 + 4];
            float4 y0 = *(const float4*)&Bs[kk][tx * 8];
            float4 y1 = *(const float4*)&Bs[kk][tx * 8 + 4];
            float a[8] = {x0.x,x0.y,x0.z,x0.w,x1.x,x1.y,x1.z,x1.w};
            float b[8] = {y0.x,y0.y,y0.z,y0.w,y1.x,y1.y,y1.z,y1.w};
            #pragma unroll
            for (int i = 0; i < 8; i++)
                #pragma unroll
                for (int j = 0; j < 8; j++) acc[i][j] += a[i] * b[j];
        }
        __syncthreads();
    }

    // Epilogue: mask, write raw logits, compute per-block-row partial stats
    float* Sz = S + (size_t)z * LQ_ * LK_;
    float2* part = g_part + ((size_t)z * 16 + blockIdx.x) * LQ_;
    #pragma unroll
    for (int i = 0; i < 8; i++) {
        const int m  = bm + ty * 8 + i;
        const int n0 = bn + tx * 8;
        const int4 m0 = *(const int4*)&mask[(size_t)m * LK_ + n0];
        const int4 m1 = *(const int4*)&mask[(size_t)m * LK_ + n0 + 4];
        acc[i][0] = m0.x ? acc[i][0] : NEGV;
        acc[i][1] = m0.y ? acc[i][1] : NEGV;
        acc[i][2] = m0.z ? acc[i][2] : NEGV;
        acc[i][3] = m0.w ? acc[i][3] : NEGV;
        acc[i][4] = m1.x ? acc[i][4] : NEGV;
        acc[i][5] = m1.y ? acc[i][5] : NEGV;
        acc[i][6] = m1.z ? acc[i][6] : NEGV;
        acc[i][7] = m1.w ? acc[i][7] : NEGV;

        float mx = acc[i][0];
        #pragma unroll
        for (int j = 1; j < 8; j++) mx = fmaxf(mx, acc[i][j]);
        #pragma unroll
        for (int o = 8; o > 0; o >>= 1)
            mx = fmaxf(mx, __shfl_xor_sync(0xffffffffu, mx, o));
        float s = 0.f;
        #pragma unroll
        for (int j = 0; j < 8; j++) s += __expf(acc[i][j] - mx);
        #pragma unroll
        for (int o = 8; o > 0; o >>= 1)
            s += __shfl_xor_sync(0xffffffffu, s, o);

        float4 w0 = {acc[i][0], acc[i][1], acc[i][2], acc[i][3]};
        float4 w1 = {acc[i][4], acc[i][5], acc[i][6], acc[i][7]};
        *(float4*)&Sz[(size_t)m * LK_ + n0]     = w0;
        *(float4*)&Sz[(size_t)m * LK_ + n0 + 4] = w1;
        if (tx == 0) part[m] = make_float2(mx, s);
    }
}

// ---------------------------------------------------------------------------
// Combine 16 partial stats per row -> {rowmax, 1/rowsum}. Tiny.
// ---------------------------------------------------------------------------
__global__ __launch_bounds__(256) void combine_kernel()
{
    const int idx = blockIdx.x * 256 + threadIdx.x;
    if (idx >= NZ * LQ_) return;
    const int z = idx >> 11, m = idx & 2047;
    const float2* p = g_part + (size_t)z * 16 * LQ_ + m;
    float M = -3.4e38f;
    #pragma unroll
    for (int tI = 0; tI < 16; tI++) M = fmaxf(M, p[(size_t)tI * LQ_].x);
    float Ssum = 0.f;
    #pragma unroll
    for (int tI = 0; tI < 16; tI++) {
        const float2 q = p[(size_t)tI * LQ_];
        Ssum += q.y * __expf(q.x - M);
    }
    g_stats[idx] = make_float2(M, 1.0f / Ssum);
}

// ---------------------------------------------------------------------------
// PV fused with normalization: reads raw logits, p = exp(s-max)/sum, writes
// normalized P back (final scores output), accumulates Oh = P @ V.
// 128(M) x 64(N) x 16(K), 256 threads, 8x4 microtile, float4 path.
// ---------------------------------------------------------------------------
__global__ __launch_bounds__(256) void pv_kernel(float* __restrict__ S)
{
    const int z  = blockIdx.y;
    const int bm = blockIdx.x * 128;
    const float* V = g_Vh + (size_t)z * LK_ * HD_;
    float* Sz = S + (size_t)z * LQ_ * LK_;

    __shared__ float Ps[16][132];
    __shared__ float Vs[16][68];
    const int t  = threadIdx.x;
    const int tx = t & 15, ty = t >> 4;
    const int r  = t >> 1, half = t & 1;     // S loader: row, col-octet
    const int vk = t >> 4, vg = t & 15;      // V loader

    const float2 st = g_stats[(size_t)z * LQ_ + bm + r];

    float acc[8][4];
    #pragma unroll
    for (int i = 0; i < 8; i++)
        #pragma unroll
        for (int j = 0; j < 4; j++) acc[i][j] = 0.f;

    for (int kt = 0; kt < LK_; kt += 16) {
        float* sp = &Sz[(size_t)(bm + r) * LK_ + kt + half * 8];
        float4 s0 = *(const float4*)(sp);
        float4 s1 = *(const float4*)(sp + 4);
        s0.x = __expf(s0.x - st.x) * st.y;
        s0.y = __expf(s0.y - st.x) * st.y;
        s0.z = __expf(s0.z - st.x) * st.y;
        s0.w = __expf(s0.w - st.x) * st.y;
        s1.x = __expf(s1.x - st.x) * st.y;
        s1.y = __expf(s1.y - st.x) * st.y;
        s1.z = __expf(s1.z - st.x) * st.y;
        s1.w = __expf(s1.w - st.x) * st.y;
        *(float4*)(sp)     = s0;             // final normalized scores
        *(float4*)(sp + 4) = s1;
        const int c = half * 8;
        Ps[c+0][r]=s0.x; Ps[c+1][r]=s0.y; Ps[c+2][r]=s0.z; Ps[c+3][r]=s0.w;
        Ps[c+4][r]=s1.x; Ps[c+5][r]=s1.y; Ps[c+6][r]=s1.z; Ps[c+7][r]=s1.w;

        *(float4*)&Vs[vk][vg * 4] = *(const float4*)&V[(size_t)(kt + vk) * HD_ + vg * 4];
        __syncthreads();
        #pragma unroll
        for (int kk = 0; kk < 16; kk++) {
            float4 x0 = *(const float4*)&Ps[kk][ty * 8];
            float4 x1 = *(const float4*)&Ps[kk][ty * 8 + 4];
            float4 b4 = *(const float4*)&Vs[kk][tx * 4];
            float a[8] = {x0.x,x0.y,x0.z,x0.w,x1.x,x1.y,x1.z,x1.w};
            #pragma unroll
            for (int i = 0; i < 8; i++) {
                acc[i][0] += a[i] * b4.x;
                acc[i][1] += a[i] * b4.y;
                acc[i][2] += a[i] * b4.z;
                acc[i][3] += a[i] * b4.w;
            }
        }
        __syncthreads();
    }

    const int bb = z >> 4, h = z & 15;
    #pragma unroll
    for (int i = 0; i < 8; i++) {
        const int q = bm + ty * 8 + i;
        float4 o = {acc[i][0], acc[i][1], acc[i][2], acc[i][3]};
        *(float4*)&g_Oh[((size_t)bb * LQ_ + q) * HDA + h * HD_ + tx * 4] = o;
    }
}

// ---------------------------------------------------------------------------
// Output GEMM: out = Oh @ wo^T + bo, M=8192, N=64, K=1024. (unchanged)
// ---------------------------------------------------------------------------
__global__ __launch_bounds__(256) void o_kernel(
    const float* __restrict__ wo, const float* __restrict__ bo,
    float* __restrict__ out)
{
    const int bm = blockIdx.x * 64;
    __shared__ float As[16][68];
    __shared__ float Ws[16][68];
    const int t  = threadIdx.x;
    const int tx = t % 16, ty = t / 16;
    const int lk = t % 16, lr = t / 16;

    float acc[4][4];
    #pragma unroll
    for (int i = 0; i < 4; i++)
        #pragma unroll
        for (int j = 0; j < 4; j++) acc[i][j] = 0.f;

    for (int kt = 0; kt < HDA; kt += 16) {
        #pragma unroll
        for (int i = 0; i < 4; i++) {
            const int m = i * 16 + lr;
            As[lk][m] = g_Oh[(size_t)(bm + m) * HDA + kt + lk];
            Ws[lk][m] = wo  [(size_t)m        * HDA + kt + lk];
        }
        __syncthreads();
        #pragma unroll
        for (int kk = 0; kk < 16; kk++) {
            float a[4], b[4];
            #pragma unroll
            for (int i = 0; i < 4; i++) a[i] = As[kk][ty * 4 + i];
            #pragma unroll
            for (int j = 0; j < 4; j++) b[j] = Ws[kk][tx + 16 * j];
            #pragma unroll
            for (int i = 0; i < 4; i++)
                #pragma unroll
                for (int j = 0; j < 4; j++) acc[i][j] += a[i] * b[j];
        }
        __syncthreads();
    }

    #pragma unroll
    for (int i = 0; i < 4; i++) {
        const int m = bm + ty * 4 + i;
        #pragma unroll
        for (int j = 0; j < 4; j++) {
            const int n = tx + 16 * j;
            out[(size_t)m * HD_ + n] = acc[i][j] + bo[n];
        }
    }
}

// ---------------------------------------------------------------------------
extern "C" void kernel_launch(void* const* d_in, const int* in_sizes, int n_in,
                              void* d_out, int out_size)
{
    (void)in_sizes; (void)n_in; (void)out_size;
    const float* q    = (const float*)d_in[0];
    const float* k    = (const float*)d_in[1];
    const float* v    = (const float*)d_in[2];
    const int*   mask = (const int*)  d_in[3];
    const float* wq   = (const float*)d_in[4];
    const float* bq   = (const float*)d_in[5];
    const float* wk   = (const float*)d_in[6];
    const float* bk   = (const float*)d_in[7];
    const float* wv   = (const float*)d_in[8];
    const float* bv   = (const float*)d_in[9];
    const float* wo   = (const float*)d_in[10];
    const float* bo   = (const float*)d_in[11];

    float* out    = (float*)d_out;                       // [B, LQ, 64]
    float* scores = out + (size_t)B_ * LQ_ * HD_;        // [B, H, LQ, LK]

    float *Qh, *Kh, *Vh;
    cudaGetSymbolAddress((void**)&Qh, g_Qh);
    cudaGetSymbolAddress((void**)&Kh, g_Kh);
    cudaGetSymbolAddress((void**)&Vh, g_Vh);

    const dim3 blk(256);
    const dim3 gproj(IND / 128, (B_ * LQ_) / 128);       // (8, 64)
    proj_kernel<<<gproj, blk>>>(q, wq, bq, Qh, 0.125f, 1);  // -> [z][d][q]
    proj_kernel<<<gproj, blk>>>(k, wk, bk, Kh, 1.0f,   1);  // -> [z][d][k]
    proj_kernel<<<gproj, blk>>>(v, wv, bv, Vh, 1.0f,   0);  // -> [z][k][d]

    const dim3 gqk(LK_ / 128, LQ_ / 128, NZ);            // (16,16,64)
    qk_kernel<<<gqk, blk>>>(mask, scores);

    combine_kernel<<<(NZ * LQ_ + 255) / 256, blk>>>();   // 512 blocks

    const dim3 gpv(LQ_ / 128, NZ);                       // (16,64)
    pv_kernel<<<gpv, blk>>>(scores);

    o_kernel<<<(B_ * LQ_) / 64, blk>>>(wo, bo, out);     // 128 blocks
}